// round 2
// baseline (speedup 1.0000x reference)
#include <cuda_runtime.h>
#include <math.h>

#define B_ 32
#define S_ 4096
#define H_ 8
#define D_ 32
#define F_ 128
#define A_ 256
#define SCALE 0.17677669529663687f   // 1/sqrt(32)

#define NCHUNK 16
#define SCHUNK 256                   // S_ / NCHUNK

// ---- scratch (static device globals; no allocations) ----
__device__ float g_u[B_][H_][F_];       // q-folded Wpk
__device__ float g_P[B_][H_][F_];       // mol_v-folded Wpo
__device__ float g_c[B_][H_];           // q·bpk per head
__device__ float g_scores[B_][S_][H_];  // raw (unscaled) scores
__device__ float g_stats[B_][H_][2];    // {max(scale*score), 1/Z}
__device__ float g_partial[B_][NCHUNK][H_][F_]; // y partial sums

// ============================================================
// K1: per-batch precompute. grid=B_, block=256
// ============================================================
__global__ void k1_precompute(const float* __restrict__ mol,
                              const float* __restrict__ Wq,  const float* __restrict__ bq,
                              const float* __restrict__ Wmv, const float* __restrict__ bmv,
                              const float* __restrict__ Wpk, const float* __restrict__ bpk,
                              const float* __restrict__ Wpo)
{
    int b = blockIdx.x;
    int t = threadIdx.x;
    __shared__ float sm_mol[F_];
    __shared__ float sq[A_];
    __shared__ float smv[A_];
    if (t < F_) sm_mol[t] = mol[b * F_ + t];
    __syncthreads();

    // q[o], mol_v[o]
    {
        float accq = bq[t], accv = bmv[t];
        const float* wq = Wq  + (size_t)t * F_;
        const float* wv = Wmv + (size_t)t * F_;
        #pragma unroll 4
        for (int i = 0; i < F_; i++) {
            float m = sm_mol[i];
            accq += wq[i] * m;
            accv += wv[i] * m;
        }
        sq[t] = accq;
        smv[t] = accv;
    }
    __syncthreads();

    // u[h][j] = sum_d q[h*32+d] * Wpk[(h*32+d)*F_ + j]   (coalesced over j)
    // P[h][j] = sum_d mv[h*32+d] * Wpo[j*A_ + (h*32+d)]
    int j = t & 127;
    int g = t >> 7;      // 0/1 -> heads 0..3 / 4..7
    #pragma unroll
    for (int hh = 0; hh < 4; hh++) {
        int h = g * 4 + hh;
        float accu = 0.f, accp = 0.f;
        #pragma unroll 8
        for (int d = 0; d < D_; d++) {
            int r = h * D_ + d;
            accu += sq[r]  * Wpk[(size_t)r * F_ + j];
            accp += smv[r] * Wpo[(size_t)j * A_ + r];
        }
        g_u[b][h][j] = accu;
        g_P[b][h][j] = accp;
    }
    if (t < H_) {
        float acc = 0.f;
        #pragma unroll
        for (int d = 0; d < D_; d++) acc += sq[t * D_ + d] * bpk[t * D_ + d];
        g_c[b][t] = acc;
    }
}

// ============================================================
// K2: stream pass 1. grid=(S_/32, B_), block=256 (8 warps x 4 rows)
// computes raw scores -> g_scores, and the FULL attended_prot_features row
// (p2m softmax is over heads: local).
// ============================================================
__global__ void __launch_bounds__(256) k2_pass1(const float* __restrict__ prot,
                                                const float* __restrict__ bpo,
                                                float* __restrict__ out2)
{
    int b = blockIdx.y;
    int s_base = blockIdx.x * 32;
    int t = threadIdx.x;
    int lane = t & 31;
    int w = t >> 5;

    __shared__ float4 su[H_][32];
    __shared__ float4 sP[H_][32];
    __shared__ float4 sbpo[32];
    __shared__ float  sc[H_];
    {
        int h = t >> 5, l = t & 31;
        su[h][l] = ((const float4*)g_u[b][h])[l];
        sP[h][l] = ((const float4*)g_P[b][h])[l];
        if (t < 32) sbpo[t] = ((const float4*)bpo)[t];
        if (t < H_) sc[t] = g_c[b][t];
    }
    __syncthreads();

    const float4* __restrict__ protr = (const float4*)(prot + (size_t)b * S_ * F_);
    float4* __restrict__ outr = (float4*)(out2 + (size_t)b * S_ * F_);

    #pragma unroll
    for (int r = 0; r < 4; r++) {
        int s = s_base + w * 4 + r;
        float4 x = protr[(size_t)s * 32 + lane];

        float p[8];
        #pragma unroll
        for (int h = 0; h < 8; h++) {
            float4 u4 = su[h][lane];
            p[h] = u4.x * x.x + u4.y * x.y + u4.z * x.z + u4.w * x.w;
        }
        #pragma unroll
        for (int off = 16; off >= 1; off >>= 1) {
            #pragma unroll
            for (int h = 0; h < 8; h++)
                p[h] += __shfl_xor_sync(0xffffffffu, p[h], off);
        }
        #pragma unroll
        for (int h = 0; h < 8; h++) p[h] += sc[h];

        // p2m softmax over heads (unscaled per reference)
        float m = p[0];
        #pragma unroll
        for (int h = 1; h < 8; h++) m = fmaxf(m, p[h]);
        float e[8], sum = 0.f;
        #pragma unroll
        for (int h = 0; h < 8; h++) { e[h] = __expf(p[h] - m); sum += e[h]; }
        float inv = 1.f / sum;

        float4 bp = sbpo[lane];
        float4 o;
        o.x = x.x + bp.x; o.y = x.y + bp.y; o.z = x.z + bp.z; o.w = x.w + bp.w;
        #pragma unroll
        for (int h = 0; h < 8; h++) {
            float wgt = e[h] * inv;
            float4 P4 = sP[h][lane];
            o.x += wgt * P4.x; o.y += wgt * P4.y; o.z += wgt * P4.z; o.w += wgt * P4.w;
        }
        outr[(size_t)s * 32 + lane] = o;

        if (lane < 8) g_scores[b][s][lane] = p[lane];
    }
}

// ============================================================
// K3: m2p softmax stats over S per (b,h). grid=B_, block=256
// ============================================================
__global__ void __launch_bounds__(256) k3_stats()
{
    int b = blockIdx.x;
    int t = threadIdx.x;
    __shared__ float red[256][9];   // padded

    float mx[8];
    #pragma unroll
    for (int h = 0; h < 8; h++) mx[h] = -1e30f;
    for (int s = t; s < S_; s += 256) {
        #pragma unroll
        for (int h = 0; h < 8; h++) mx[h] = fmaxf(mx[h], g_scores[b][s][h]);
    }
    #pragma unroll
    for (int h = 0; h < 8; h++) red[t][h] = mx[h];
    __syncthreads();
    for (int off = 128; off > 0; off >>= 1) {
        if (t < off) {
            #pragma unroll
            for (int h = 0; h < 8; h++) red[t][h] = fmaxf(red[t][h], red[t + off][h]);
        }
        __syncthreads();
    }
    float M[8];
    #pragma unroll
    for (int h = 0; h < 8; h++) M[h] = SCALE * red[0][h];
    __syncthreads();

    float sm[8];
    #pragma unroll
    for (int h = 0; h < 8; h++) sm[h] = 0.f;
    for (int s = t; s < S_; s += 256) {
        #pragma unroll
        for (int h = 0; h < 8; h++)
            sm[h] += __expf(SCALE * g_scores[b][s][h] - M[h]);
    }
    #pragma unroll
    for (int h = 0; h < 8; h++) red[t][h] = sm[h];
    __syncthreads();
    for (int off = 128; off > 0; off >>= 1) {
        if (t < off) {
            #pragma unroll
            for (int h = 0; h < 8; h++) red[t][h] += red[t + off][h];
        }
        __syncthreads();
    }
    if (t < H_) {
        g_stats[b][t][0] = M[t];
        g_stats[b][t][1] = 1.f / red[0][t];
    }
}

// ============================================================
// K4: stream pass 2. grid=(NCHUNK, B_), block=256
// m2p weights -> avg output, y partial accumulation (deterministic).
// ============================================================
__global__ void __launch_bounds__(256) k4_pass2(const float* __restrict__ prot,
                                                float* __restrict__ out3)
{
    int b = blockIdx.y;
    int ci = blockIdx.x;
    int t = threadIdx.x;
    int s0 = ci * SCHUNK;

    __shared__ float wbuf[SCHUNK][8];
    __shared__ float M[8], Z[8];
    if (t < 8) { M[t] = g_stats[b][t][0]; Z[t] = g_stats[b][t][1]; }
    __syncthreads();

    // phase A: weights + avg
    {
        int s = s0 + t;
        float sum = 0.f;
        #pragma unroll
        for (int h = 0; h < 8; h++) {
            float wv = __expf(SCALE * g_scores[b][s][h] - M[h]) * Z[h];
            wbuf[t][h] = wv;
            sum += wv;
        }
        out3[(size_t)b * S_ + s] = sum * 0.125f;
    }
    __syncthreads();

    // phase B: y[h][j] partials over this chunk
    int j = t & 127;
    int g = t >> 7;
    int h0 = g * 4;
    float acc0 = 0.f, acc1 = 0.f, acc2 = 0.f, acc3 = 0.f;
    const float* __restrict__ xp = prot + ((size_t)b * S_ + s0) * F_ + j;
    #pragma unroll 4
    for (int s = 0; s < SCHUNK; s++) {
        float xj = __ldg(xp + (size_t)s * F_);
        acc0 += wbuf[s][h0 + 0] * xj;
        acc1 += wbuf[s][h0 + 1] * xj;
        acc2 += wbuf[s][h0 + 2] * xj;
        acc3 += wbuf[s][h0 + 3] * xj;
    }
    g_partial[b][ci][h0 + 0][j] = acc0;
    g_partial[b][ci][h0 + 1][j] = acc1;
    g_partial[b][ci][h0 + 2][j] = acc2;
    g_partial[b][ci][h0 + 3][j] = acc3;
}

// ============================================================
// K5: epilogue -> attended_mol_features. grid=B_, block=256
// ============================================================
__global__ void __launch_bounds__(256) k5_epilogue(const float* __restrict__ mol,
                                                   const float* __restrict__ Wpv,
                                                   const float* __restrict__ bpv,
                                                   const float* __restrict__ Wmo,
                                                   const float* __restrict__ bmo,
                                                   float* __restrict__ out1)
{
    int b = blockIdx.x;
    int t = threadIdx.x;
    __shared__ float y[H_][F_];
    __shared__ float ap[A_];

    #pragma unroll
    for (int k = 0; k < 4; k++) {
        int idx = k * 256 + t;
        float acc = 0.f;
        #pragma unroll
        for (int c = 0; c < NCHUNK; c++)
            acc += ((const float*)g_partial[b][c])[idx];
        ((float*)y)[idx] = acc;
    }
    __syncthreads();

    {
        int o = t;
        int h = o >> 5;
        float acc = bpv[o];
        const float* wr = Wpv + (size_t)o * F_;
        #pragma unroll 4
        for (int jj = 0; jj < F_; jj++) acc += wr[jj] * y[h][jj];
        ap[o] = acc;
    }
    __syncthreads();

    if (t < F_) {
        float acc = bmo[t] + mol[(size_t)b * F_ + t];
        const float* wr = Wmo + (size_t)t * A_;
        #pragma unroll 4
        for (int o = 0; o < A_; o++) acc += wr[o] * ap[o];
        out1[(size_t)b * F_ + t] = acc;
    }
}

// ============================================================
extern "C" void kernel_launch(void* const* d_in, const int* in_sizes, int n_in,
                              void* d_out, int out_size)
{
    const float* mol  = (const float*)d_in[0];
    const float* prot = (const float*)d_in[1];
    const float* Wq   = (const float*)d_in[2];
    const float* bq   = (const float*)d_in[3];
    const float* Wmv  = (const float*)d_in[4];
    const float* bmv  = (const float*)d_in[5];
    const float* Wpk  = (const float*)d_in[6];
    const float* bpk  = (const float*)d_in[7];
    const float* Wpv  = (const float*)d_in[8];
    const float* bpv  = (const float*)d_in[9];
    const float* Wmo  = (const float*)d_in[10];
    const float* bmo  = (const float*)d_in[11];
    const float* Wpo  = (const float*)d_in[12];
    const float* bpo  = (const float*)d_in[13];

    float* out = (float*)d_out;
    float* out1 = out;                                    // [B,128]
    float* out2 = out + (size_t)B_ * F_;                  // [B,S,128]
    float* out3 = out + (size_t)B_ * F_ + (size_t)B_ * S_ * F_;  // [B,S]

    k1_precompute<<<B_, 256>>>(mol, Wq, bq, Wmv, bmv, Wpk, bpk, Wpo);
    k2_pass1<<<dim3(S_ / 32, B_), 256>>>(prot, bpo, out2);
    k3_stats<<<B_, 256>>>();
    k4_pass2<<<dim3(NCHUNK, B_), 256>>>(prot, out3);
    k5_epilogue<<<B_, 256>>>(mol, Wpv, bpv, Wmo, bmo, out1);
}

// round 3
// speedup vs baseline: 1.1661x; 1.1661x over previous
#include <cuda_runtime.h>
#include <math.h>

#define B_ 32
#define S_ 4096
#define H_ 8
#define D_ 32
#define F_ 128
#define A_ 256
#define SCALE 0.17677669529663687f   // 1/sqrt(32)

#define CH 128                 // S-rows per chunk (per block in k2)
#define NCH (S_ / CH)          // 32 chunks per batch
#define XS_STRIDE 132          // padded row stride (floats) for smem x tile

// ---- scratch (static device globals; no allocations) ----
__device__ float g_u[B_][H_][F_];        // q-folded Wpk
__device__ float g_P[B_][H_][F_];        // mol_v-folded Wpo
__device__ float g_c[B_][H_];            // q·bpk per head
__device__ float g_scores[B_][S_][H_];   // raw (unscaled) scores
__device__ float g_stats[B_][H_][2];     // {M, 1/Z} for m2p softmax
__device__ float g_pm[B_][NCH][H_];      // chunk-local max (scaled)
__device__ float g_pz[B_][NCH][H_];      // chunk-local sumexp
__device__ float g_py[B_][NCH][H_][F_];  // chunk-local weighted sums

// dynamic smem size for k2 (floats):
// xs 128*132 | us 8*132 | Ps 8*128 | bpos 128 | cs 8 | sc 128*9 | ew 128*8
// red2 256 | redm 256 | mloc 8 | zloc 8
#define K2_SMEM_FLOATS (CH*XS_STRIDE + H_*XS_STRIDE + H_*F_ + F_ + H_ + CH*9 + CH*H_ + 256 + 256 + H_ + H_)
#define K2_SMEM_BYTES (K2_SMEM_FLOATS * 4)

// ============================================================
// K1: per-batch precompute. grid=B_, block=256
// ============================================================
__global__ void k1_precompute(const float* __restrict__ mol,
                              const float* __restrict__ Wq,  const float* __restrict__ bq,
                              const float* __restrict__ Wmv, const float* __restrict__ bmv,
                              const float* __restrict__ Wpk, const float* __restrict__ bpk,
                              const float* __restrict__ Wpo)
{
    int b = blockIdx.x;
    int t = threadIdx.x;
    __shared__ float sm_mol[F_];
    __shared__ float sq[A_];
    __shared__ float smv[A_];
    if (t < F_) sm_mol[t] = mol[b * F_ + t];
    __syncthreads();

    {
        float accq = bq[t], accv = bmv[t];
        const float* wq = Wq  + (size_t)t * F_;
        const float* wv = Wmv + (size_t)t * F_;
        #pragma unroll 4
        for (int i = 0; i < F_; i++) {
            float m = sm_mol[i];
            accq += wq[i] * m;
            accv += wv[i] * m;
        }
        sq[t] = accq;
        smv[t] = accv;
    }
    __syncthreads();

    int j = t & 127;
    int g = t >> 7;
    #pragma unroll
    for (int hh = 0; hh < 4; hh++) {
        int h = g * 4 + hh;
        float accu = 0.f, accp = 0.f;
        #pragma unroll 8
        for (int d = 0; d < D_; d++) {
            int r = h * D_ + d;
            accu += sq[r]  * Wpk[(size_t)r * F_ + j];
            accp += smv[r] * Wpo[(size_t)j * A_ + r];
        }
        g_u[b][h][j] = accu;
        g_P[b][h][j] = accp;
    }
    if (t < H_) {
        float acc = 0.f;
        #pragma unroll
        for (int d = 0; d < D_; d++) acc += sq[t * D_ + d] * bpk[t * D_ + d];
        g_c[b][t] = acc;
    }
}

// ============================================================
// K2: single fused pass over prot. grid=(NCH, B_), block=256.
// Stages a 128x128 chunk in smem, then:
//  B1: scores (shuffle-free)      B2: p2m softmax + out2 + score store
//  B3: chunk-local m2p stats (m, Z, y) -> partials
// ============================================================
__global__ void __launch_bounds__(256) k2_fused(const float* __restrict__ prot,
                                                const float* __restrict__ bpo,
                                                float* __restrict__ out2)
{
    extern __shared__ float sm[];
    float* xs   = sm;                        // [CH][XS_STRIDE]
    float* us   = xs + CH * XS_STRIDE;       // [H][XS_STRIDE]
    float* Ps   = us + H_ * XS_STRIDE;       // [H][F]
    float* bpos = Ps + H_ * F_;              // [F]
    float* cs   = bpos + F_;                 // [H]
    float* sc   = cs + H_;                   // [CH][9]
    float* ew   = sc + CH * 9;               // [CH][H]
    float* red2 = ew + CH * H_;              // [256]
    float* redm = red2 + 256;                // [32][8]
    float* mloc = redm + 256;                // [8]
    float* zloc = mloc + H_;                 // [8]

    int b = blockIdx.y;
    int ch = blockIdx.x;
    int s0 = ch * CH;
    int t = threadIdx.x;
    int lane = t & 31;
    int w = t >> 5;

    // constants into smem
    #pragma unroll
    for (int k = 0; k < 4; k++) {
        int idx = t + 256 * k;               // 0..1023
        int h = idx >> 7, j = idx & 127;
        us[h * XS_STRIDE + j] = g_u[b][h][j];
        Ps[h * F_ + j]        = g_P[b][h][j];
    }
    if (t < F_) bpos[t] = bpo[t];
    if (t < H_) cs[t] = g_c[b][t];

    // ---- phase A: stage prot chunk (coalesced, MLP=16) ----
    const float4* __restrict__ protr = (const float4*)(prot + ((size_t)b * S_ + s0) * F_);
    #pragma unroll
    for (int k = 0; k < 16; k++) {
        int i = t + 256 * k;                 // float4 index 0..4095
        int row = i >> 5, j4 = i & 31;
        float4 v = protr[i];
        *(float4*)(xs + row * XS_STRIDE + j4 * 4) = v;
    }
    __syncthreads();

    // ---- phase B1: scores (thread = (s-lane, h)) ----
    {
        int h = t & 7;
        int sl = t >> 3;                     // 0..31
        const float4* u4 = (const float4*)(us + h * XS_STRIDE);
        #pragma unroll
        for (int k = 0; k < 4; k++) {
            int s = sl + 32 * k;
            const float4* x4 = (const float4*)(xs + s * XS_STRIDE);
            float acc = cs[h];
            #pragma unroll 8
            for (int j4 = 0; j4 < 32; j4++) {
                float4 uu = u4[j4], xx = x4[j4];
                acc += uu.x * xx.x + uu.y * xx.y + uu.z * xx.z + uu.w * xx.w;
            }
            sc[s * 9 + h] = acc;
        }
    }
    __syncthreads();

    // ---- phase B2: p2m softmax (over heads, unscaled) + out2 + score store ----
    float4* __restrict__ outr = (float4*)(out2 + ((size_t)b * S_ + s0) * F_);
    #pragma unroll 2
    for (int r = 0; r < 16; r++) {
        int s = w * 16 + r;
        float p[8];
        #pragma unroll
        for (int h = 0; h < 8; h++) p[h] = sc[s * 9 + h];

        float m = p[0];
        #pragma unroll
        for (int h = 1; h < 8; h++) m = fmaxf(m, p[h]);
        float e[8], sum = 0.f;
        #pragma unroll
        for (int h = 0; h < 8; h++) { e[h] = __expf(p[h] - m); sum += e[h]; }
        float inv = 1.f / sum;

        float4 x  = *(const float4*)(xs + s * XS_STRIDE + lane * 4);
        float4 bp = ((const float4*)bpos)[lane];
        float4 o;
        o.x = x.x + bp.x; o.y = x.y + bp.y; o.z = x.z + bp.z; o.w = x.w + bp.w;
        #pragma unroll
        for (int h = 0; h < 8; h++) {
            float wgt = e[h] * inv;
            float4 P4 = ((const float4*)(Ps + h * F_))[lane];
            o.x += wgt * P4.x; o.y += wgt * P4.y; o.z += wgt * P4.z; o.w += wgt * P4.w;
        }
        outr[s * 32 + lane] = o;
        if (lane < 8) g_scores[b][s0 + s][lane] = p[lane];
    }

    // ---- phase B3a: chunk-local max, e-weights, Z ----
    {
        int h = t & 7, sg = t >> 3;
        float mx = -1e30f;
        #pragma unroll
        for (int k = 0; k < 4; k++) mx = fmaxf(mx, sc[(sg * 4 + k) * 9 + h]);
        redm[sg * 8 + h] = mx;
    }
    __syncthreads();
    if (t < 8) {
        float mx = -1e30f;
        #pragma unroll 8
        for (int i = 0; i < 32; i++) mx = fmaxf(mx, redm[i * 8 + t]);
        mloc[t] = SCALE * mx;
    }
    __syncthreads();
    {
        int h = t & 7;
        float mh = mloc[h];
        float zp = 0.f;
        #pragma unroll
        for (int k = 0; k < 4; k++) {
            int idx = t + 256 * k;
            int s = idx >> 3;
            float e = __expf(SCALE * sc[s * 9 + h] - mh);
            ew[s * 8 + h] = e;
            zp += e;
        }
        red2[t] = zp;
    }
    __syncthreads();
    if (t < 8) {
        float z = 0.f;
        #pragma unroll 8
        for (int i = 0; i < 32; i++) z += red2[t + i * 8];
        zloc[t] = z;
        g_pm[b][ch][t] = mloc[t];
        g_pz[b][ch][t] = z;
    }
    __syncthreads();

    // ---- phase B3b: chunk-local weighted sums y (thread = (h, j4)) ----
    {
        int j4 = t & 31;
        int h = t >> 5;
        float4 acc = make_float4(0.f, 0.f, 0.f, 0.f);
        #pragma unroll 4
        for (int s = 0; s < CH; s++) {
            float4 x = *(const float4*)(xs + s * XS_STRIDE + j4 * 4);
            float e = ew[s * 8 + h];
            acc.x += e * x.x; acc.y += e * x.y; acc.z += e * x.z; acc.w += e * x.w;
        }
        *(float4*)(&g_py[b][ch][h][j4 * 4]) = acc;
    }
}

// ============================================================
// K3: combine chunk partials + full epilogue -> out1, g_stats.
// grid=B_, block=256
// ============================================================
__global__ void __launch_bounds__(256) k3_epilogue(const float* __restrict__ mol,
                                                   const float* __restrict__ Wpv,
                                                   const float* __restrict__ bpv,
                                                   const float* __restrict__ Wmo,
                                                   const float* __restrict__ bmo,
                                                   float* __restrict__ out1)
{
    int b = blockIdx.x;
    int t = threadIdx.x;
    __shared__ float iZ[H_];
    __shared__ float fch[NCH][H_];
    __shared__ float ys[H_][F_];
    __shared__ float ap[A_];

    if (t < H_) {
        float M = -1e30f;
        #pragma unroll 8
        for (int c = 0; c < NCH; c++) M = fmaxf(M, g_pm[b][c][t]);
        float Z = 0.f;
        for (int c = 0; c < NCH; c++) {
            float f = __expf(g_pm[b][c][t] - M);
            fch[c][t] = f;
            Z += g_pz[b][c][t] * f;
        }
        iZ[t] = 1.f / Z;
        g_stats[b][t][0] = M;
        g_stats[b][t][1] = 1.f / Z;
    }
    __syncthreads();

    #pragma unroll
    for (int k = 0; k < 4; k++) {
        int idx = t + 256 * k;               // h*128 + j
        int h = idx >> 7, j = idx & 127;
        float acc = 0.f;
        #pragma unroll 8
        for (int c = 0; c < NCH; c++)
            acc += g_py[b][c][h][j] * fch[c][h];
        ys[h][j] = acc * iZ[h];
    }
    __syncthreads();

    {
        int o = t;
        int h = o >> 5;
        float acc = bpv[o];
        const float* wr = Wpv + (size_t)o * F_;
        #pragma unroll 4
        for (int j = 0; j < F_; j++) acc += wr[j] * ys[h][j];
        ap[o] = acc;
    }
    __syncthreads();

    if (t < F_) {
        float acc = bmo[t] + mol[(size_t)b * F_ + t];
        const float* wr = Wmo + (size_t)t * A_;
        #pragma unroll 4
        for (int o = 0; o < A_; o++) acc += wr[o] * ap[o];
        out1[(size_t)b * F_ + t] = acc;
    }
}

// ============================================================
// K4: avg attention weights. grid=(S_/256, B_), block=256
// ============================================================
__global__ void __launch_bounds__(256) k4_avg(float* __restrict__ out3)
{
    int b = blockIdx.y;
    int s = blockIdx.x * 256 + threadIdx.x;
    __shared__ float Ms[H_], iZ[H_];
    if (threadIdx.x < H_) {
        Ms[threadIdx.x] = g_stats[b][threadIdx.x][0];
        iZ[threadIdx.x] = g_stats[b][threadIdx.x][1];
    }
    __syncthreads();

    float4 a = *(const float4*)&g_scores[b][s][0];
    float4 c = *(const float4*)&g_scores[b][s][4];
    float sum = __expf(SCALE * a.x - Ms[0]) * iZ[0]
              + __expf(SCALE * a.y - Ms[1]) * iZ[1]
              + __expf(SCALE * a.z - Ms[2]) * iZ[2]
              + __expf(SCALE * a.w - Ms[3]) * iZ[3]
              + __expf(SCALE * c.x - Ms[4]) * iZ[4]
              + __expf(SCALE * c.y - Ms[5]) * iZ[5]
              + __expf(SCALE * c.z - Ms[6]) * iZ[6]
              + __expf(SCALE * c.w - Ms[7]) * iZ[7];
    out3[(size_t)b * S_ + s] = sum * 0.125f;
}

// ============================================================
extern "C" void kernel_launch(void* const* d_in, const int* in_sizes, int n_in,
                              void* d_out, int out_size)
{
    const float* mol  = (const float*)d_in[0];
    const float* prot = (const float*)d_in[1];
    const float* Wq   = (const float*)d_in[2];
    const float* bq   = (const float*)d_in[3];
    const float* Wmv  = (const float*)d_in[4];
    const float* bmv  = (const float*)d_in[5];
    const float* Wpk  = (const float*)d_in[6];
    const float* bpk  = (const float*)d_in[7];
    const float* Wpv  = (const float*)d_in[8];
    const float* bpv  = (const float*)d_in[9];
    const float* Wmo  = (const float*)d_in[10];
    const float* bmo  = (const float*)d_in[11];
    const float* Wpo  = (const float*)d_in[12];
    const float* bpo  = (const float*)d_in[13];

    float* out = (float*)d_out;
    float* out1 = out;                                           // [B,128]
    float* out2 = out + (size_t)B_ * F_;                         // [B,S,128]
    float* out3 = out + (size_t)B_ * F_ + (size_t)B_ * S_ * F_;  // [B,S]

    cudaFuncSetAttribute(k2_fused, cudaFuncAttributeMaxDynamicSharedMemorySize,
                         K2_SMEM_BYTES);

    k1_precompute<<<B_, 256>>>(mol, Wq, bq, Wmv, bmv, Wpk, bpk, Wpo);
    k2_fused<<<dim3(NCH, B_), 256, K2_SMEM_BYTES>>>(prot, bpo, out2);
    k3_epilogue<<<B_, 256>>>(mol, Wpv, bpv, Wmo, bmo, out1);
    k4_avg<<<dim3(S_ / 256, B_), 256>>>(out3);
}

// round 4
// speedup vs baseline: 1.5619x; 1.3394x over previous
#include <cuda_runtime.h>
#include <math.h>

#define B_ 32
#define S_ 4096
#define H_ 8
#define D_ 32
#define F_ 128
#define A_ 256
#define SCALE 0.17677669529663687f   // 1/sqrt(32)

#define CH 64                  // S-rows per chunk (per block in k2)
#define NCH (S_ / CH)          // 64 chunks per batch
#define XS_STRIDE 132          // padded row stride (floats) for smem x tile

// ---- scratch (static device globals; no allocations) ----
__device__ float g_u[B_][H_][F_];        // q-folded Wpk
__device__ float g_P[B_][H_][F_];        // mol_v-folded Wpo
__device__ float g_c[B_][H_];            // q·bpk per head
__device__ float g_scores[B_][S_][H_];   // raw (unscaled) scores
__device__ float g_stats[B_][H_][2];     // {M, 1/Z} for m2p softmax
__device__ float g_pm[B_][NCH][H_];      // chunk-local max (scaled)
__device__ float g_pz[B_][NCH][H_];      // chunk-local sumexp
__device__ float g_py[B_][NCH][H_][F_];  // chunk-local weighted sums

// k2 dynamic smem (floats):
// xs 64*132 | us 8*132 | Ps 8*128 | bpos 128 | cs 8 | sc 64*9 | ew 64*8
// red2 256 | redm 256 | mloc 8 | zloc 8
#define K2_SMEM_FLOATS (CH*XS_STRIDE + H_*XS_STRIDE + H_*F_ + F_ + H_ + CH*9 + CH*H_ + 256 + 256 + H_ + H_)
#define K2_SMEM_BYTES (K2_SMEM_FLOATS * 4)

// ============================================================
// K1: per-batch precompute, ALL global reads coalesced.
// grid=B_, block=256 (8 warps)
// ============================================================
__global__ void __launch_bounds__(256) k1_precompute(
    const float* __restrict__ mol,
    const float* __restrict__ Wq,  const float* __restrict__ bq,
    const float* __restrict__ Wmv, const float* __restrict__ bmv,
    const float* __restrict__ Wpk, const float* __restrict__ bpk,
    const float* __restrict__ Wpo)
{
    int b = blockIdx.x;
    int t = threadIdx.x;
    int lane = t & 31;
    int w = t >> 5;
    __shared__ float sm_mol[F_];
    __shared__ float sq[A_];
    __shared__ float smv[A_];
    if (t < F_) sm_mol[t] = mol[b * F_ + t];
    __syncthreads();

    // ---- q[o], mv[o]: warp-cooperative coalesced row dots ----
    {
        float4 m4 = *(const float4*)(sm_mol + lane * 4);
        #pragma unroll 4
        for (int rr = 0; rr < 32; rr++) {
            int o = w * 32 + rr;
            float4 a = ((const float4*)(Wq  + (size_t)o * F_))[lane];
            float4 v = ((const float4*)(Wmv + (size_t)o * F_))[lane];
            float accq = a.x * m4.x + a.y * m4.y + a.z * m4.z + a.w * m4.w;
            float accv = v.x * m4.x + v.y * m4.y + v.z * m4.z + v.w * m4.w;
            #pragma unroll
            for (int off = 16; off >= 1; off >>= 1) {
                accq += __shfl_xor_sync(0xffffffffu, accq, off);
                accv += __shfl_xor_sync(0xffffffffu, accv, off);
            }
            if (lane == 0) {
                sq[o]  = accq + bq[o];
                smv[o] = accv + bmv[o];
            }
        }
    }
    __syncthreads();

    // ---- u[h][j]: coalesced over j (lane-consecutive) ----
    {
        int j = t & 127;
        int g = t >> 7;
        #pragma unroll
        for (int hh = 0; hh < 4; hh++) {
            int h = g * 4 + hh;
            float accu = 0.f;
            #pragma unroll 8
            for (int d = 0; d < D_; d++) {
                int r = h * D_ + d;
                accu += sq[r] * Wpk[(size_t)r * F_ + j];
            }
            g_u[b][h][j] = accu;
        }
    }

    // ---- P[h][j]: warp-per-j coalesced Wpo row reads, segmented reduce ----
    {
        #pragma unroll 4
        for (int jj = 0; jj < 16; jj++) {
            int j = w * 16 + jj;
            const float4* wr = (const float4*)(Wpo + (size_t)j * A_);
            // lane covers r = lane*4..lane*4+3 (a0, heads 0-3) and r+128 (a1, heads 4-7)
            float4 w0 = wr[lane];
            float4 w1 = wr[lane + 32];
            float4 v0 = *(const float4*)(smv + lane * 4);
            float4 v1 = *(const float4*)(smv + 128 + lane * 4);
            float a0 = w0.x * v0.x + w0.y * v0.y + w0.z * v0.z + w0.w * v0.w;
            float a1 = w1.x * v1.x + w1.y * v1.y + w1.z * v1.z + w1.w * v1.w;
            #pragma unroll
            for (int off = 1; off <= 4; off <<= 1) {
                a0 += __shfl_xor_sync(0xffffffffu, a0, off);
                a1 += __shfl_xor_sync(0xffffffffu, a1, off);
            }
            if ((lane & 7) == 0) {
                int hg = lane >> 3;          // 0..3
                g_P[b][hg][j]     = a0;
                g_P[b][4 + hg][j] = a1;
            }
        }
    }

    if (t < H_) {
        float acc = 0.f;
        #pragma unroll
        for (int d = 0; d < D_; d++) acc += sq[t * D_ + d] * bpk[t * D_ + d];
        g_c[b][t] = acc;
    }
}

// ============================================================
// K2: single fused pass over prot. grid=(NCH, B_), block=256.
// ============================================================
__global__ void __launch_bounds__(256) k2_fused(const float* __restrict__ prot,
                                                const float* __restrict__ bpo,
                                                float* __restrict__ out2)
{
    extern __shared__ float sm[];
    float* xs   = sm;                        // [CH][XS_STRIDE]
    float* us   = xs + CH * XS_STRIDE;       // [H][XS_STRIDE]
    float* Ps   = us + H_ * XS_STRIDE;       // [H][F]
    float* bpos = Ps + H_ * F_;              // [F]
    float* cs   = bpos + F_;                 // [H]
    float* sc   = cs + H_;                   // [CH][9]
    float* ew   = sc + CH * 9;               // [CH][H]
    float* red2 = ew + CH * H_;              // [256]
    float* redm = red2 + 256;                // [32][8]
    float* mloc = redm + 256;                // [8]
    float* zloc = mloc + H_;                 // [8]

    int b = blockIdx.y;
    int ch = blockIdx.x;
    int s0 = ch * CH;
    int t = threadIdx.x;
    int lane = t & 31;
    int w = t >> 5;

    // constants into smem
    #pragma unroll
    for (int k = 0; k < 4; k++) {
        int idx = t + 256 * k;               // 0..1023
        int h = idx >> 7, j = idx & 127;
        us[h * XS_STRIDE + j] = g_u[b][h][j];
        Ps[h * F_ + j]        = g_P[b][h][j];
    }
    if (t < F_) bpos[t] = bpo[t];
    if (t < H_) cs[t] = g_c[b][t];

    // ---- phase A: stage prot chunk (coalesced, streaming) ----
    const float4* __restrict__ protr = (const float4*)(prot + ((size_t)b * S_ + s0) * F_);
    #pragma unroll
    for (int k = 0; k < 8; k++) {
        int i = t + 256 * k;                 // float4 index 0..2047
        int row = i >> 5, j4 = i & 31;
        float4 v = __ldcs(protr + i);
        *(float4*)(xs + row * XS_STRIDE + j4 * 4) = v;
    }
    __syncthreads();

    // ---- phase B1: scores (thread = (s-lane, h)), shuffle-free ----
    {
        int h = t & 7;
        int sl = t >> 3;                     // 0..31
        const float4* u4 = (const float4*)(us + h * XS_STRIDE);
        #pragma unroll
        for (int k = 0; k < 2; k++) {
            int s = sl + 32 * k;
            const float4* x4 = (const float4*)(xs + s * XS_STRIDE);
            float acc = cs[h];
            #pragma unroll 8
            for (int j4 = 0; j4 < 32; j4++) {
                float4 uu = u4[j4], xx = x4[j4];
                acc += uu.x * xx.x + uu.y * xx.y + uu.z * xx.z + uu.w * xx.w;
            }
            sc[s * 9 + h] = acc;
        }
    }
    __syncthreads();

    // ---- coalesced raw-score store (512 contiguous floats) ----
    {
        float* gs = &g_scores[b][s0][0];
        #pragma unroll
        for (int k = 0; k < 2; k++) {
            int idx = t + 256 * k;           // s*8 + h
            gs[idx] = sc[(idx >> 3) * 9 + (idx & 7)];
        }
    }

    // ---- phase B2: p2m softmax (over heads, unscaled) + out2 ----
    float4* __restrict__ outr = (float4*)(out2 + ((size_t)b * S_ + s0) * F_);
    #pragma unroll 2
    for (int r = 0; r < 8; r++) {
        int s = w * 8 + r;
        float p[8];
        #pragma unroll
        for (int h = 0; h < 8; h++) p[h] = sc[s * 9 + h];

        float m = p[0];
        #pragma unroll
        for (int h = 1; h < 8; h++) m = fmaxf(m, p[h]);
        float e[8], sum = 0.f;
        #pragma unroll
        for (int h = 0; h < 8; h++) { e[h] = __expf(p[h] - m); sum += e[h]; }
        float inv = 1.f / sum;

        float4 x  = *(const float4*)(xs + s * XS_STRIDE + lane * 4);
        float4 bp = ((const float4*)bpos)[lane];
        float4 o;
        o.x = x.x + bp.x; o.y = x.y + bp.y; o.z = x.z + bp.z; o.w = x.w + bp.w;
        #pragma unroll
        for (int h = 0; h < 8; h++) {
            float wgt = e[h] * inv;
            float4 P4 = ((const float4*)(Ps + h * F_))[lane];
            o.x += wgt * P4.x; o.y += wgt * P4.y; o.z += wgt * P4.z; o.w += wgt * P4.w;
        }
        __stcs(outr + s * 32 + lane, o);
    }

    // ---- phase B3a: chunk-local max, e-weights, Z ----
    {
        int h = t & 7, sg = t >> 3;          // sg 0..31, rows sg*2..sg*2+1
        float mx = fmaxf(sc[(sg * 2) * 9 + h], sc[(sg * 2 + 1) * 9 + h]);
        redm[sg * 8 + h] = mx;
    }
    __syncthreads();
    if (t < 8) {
        float mx = -1e30f;
        #pragma unroll 8
        for (int i = 0; i < 32; i++) mx = fmaxf(mx, redm[i * 8 + t]);
        mloc[t] = SCALE * mx;
    }
    __syncthreads();
    {
        int h = t & 7;
        float mh = mloc[h];
        float zp = 0.f;
        #pragma unroll
        for (int k = 0; k < 2; k++) {
            int idx = t + 256 * k;
            int s = idx >> 3;
            float e = __expf(SCALE * sc[s * 9 + h] - mh);
            ew[s * 8 + h] = e;
            zp += e;
        }
        red2[t] = zp;
    }
    __syncthreads();
    if (t < 8) {
        float z = 0.f;
        #pragma unroll 8
        for (int i = 0; i < 32; i++) z += red2[t + i * 8];
        zloc[t] = z;
        g_pm[b][ch][t] = mloc[t];
        g_pz[b][ch][t] = z;
    }
    __syncthreads();

    // ---- phase B3b: chunk-local weighted sums y (thread = (h, j4)) ----
    {
        int j4 = t & 31;
        int h = t >> 5;
        float4 acc = make_float4(0.f, 0.f, 0.f, 0.f);
        #pragma unroll 4
        for (int s = 0; s < CH; s++) {
            float4 x = *(const float4*)(xs + s * XS_STRIDE + j4 * 4);
            float e = ew[s * 8 + h];
            acc.x += e * x.x; acc.y += e * x.y; acc.z += e * x.z; acc.w += e * x.w;
        }
        *(float4*)(&g_py[b][ch][h][j4 * 4]) = acc;
    }
}

// ============================================================
// K3: combine chunk partials + full epilogue -> out1, g_stats.
// grid=B_, block=256
// ============================================================
__global__ void __launch_bounds__(256) k3_epilogue(const float* __restrict__ mol,
                                                   const float* __restrict__ Wpv,
                                                   const float* __restrict__ bpv,
                                                   const float* __restrict__ Wmo,
                                                   const float* __restrict__ bmo,
                                                   float* __restrict__ out1)
{
    int b = blockIdx.x;
    int t = threadIdx.x;
    __shared__ float iZ[H_];
    __shared__ float fch[NCH][H_];
    __shared__ float ys[H_][F_];
    __shared__ float ap[A_];

    if (t < H_) {
        float M = -1e30f;
        #pragma unroll 8
        for (int c = 0; c < NCH; c++) M = fmaxf(M, g_pm[b][c][t]);
        float Z = 0.f;
        for (int c = 0; c < NCH; c++) {
            float f = __expf(g_pm[b][c][t] - M);
            fch[c][t] = f;
            Z += g_pz[b][c][t] * f;
        }
        iZ[t] = 1.f / Z;
        g_stats[b][t][0] = M;
        g_stats[b][t][1] = 1.f / Z;
    }
    __syncthreads();

    #pragma unroll
    for (int k = 0; k < 4; k++) {
        int idx = t + 256 * k;               // h*128 + j
        int h = idx >> 7, j = idx & 127;
        float acc = 0.f;
        #pragma unroll 8
        for (int c = 0; c < NCH; c++)
            acc += g_py[b][c][h][j] * fch[c][h];
        ys[h][j] = acc * iZ[h];
    }
    __syncthreads();

    {
        int o = t;
        int h = o >> 5;
        float acc = bpv[o];
        const float* wr = Wpv + (size_t)o * F_;
        #pragma unroll 4
        for (int j = 0; j < F_; j++) acc += wr[j] * ys[h][j];
        ap[o] = acc;
    }
    __syncthreads();

    if (t < F_) {
        float acc = bmo[t] + mol[(size_t)b * F_ + t];
        const float* wr = Wmo + (size_t)t * A_;
        #pragma unroll 4
        for (int o = 0; o < A_; o++) acc += wr[o] * ap[o];
        out1[(size_t)b * F_ + t] = acc;
    }
}

// ============================================================
// K4: avg attention weights. grid=(S_/256, B_), block=256
// ============================================================
__global__ void __launch_bounds__(256) k4_avg(float* __restrict__ out3)
{
    int b = blockIdx.y;
    int s = blockIdx.x * 256 + threadIdx.x;
    __shared__ float Ms[H_], iZ[H_];
    if (threadIdx.x < H_) {
        Ms[threadIdx.x] = g_stats[b][threadIdx.x][0];
        iZ[threadIdx.x] = g_stats[b][threadIdx.x][1];
    }
    __syncthreads();

    float4 a = *(const float4*)&g_scores[b][s][0];
    float4 c = *(const float4*)&g_scores[b][s][4];
    float sum = __expf(SCALE * a.x - Ms[0]) * iZ[0]
              + __expf(SCALE * a.y - Ms[1]) * iZ[1]
              + __expf(SCALE * a.z - Ms[2]) * iZ[2]
              + __expf(SCALE * a.w - Ms[3]) * iZ[3]
              + __expf(SCALE * c.x - Ms[4]) * iZ[4]
              + __expf(SCALE * c.y - Ms[5]) * iZ[5]
              + __expf(SCALE * c.z - Ms[6]) * iZ[6]
              + __expf(SCALE * c.w - Ms[7]) * iZ[7];
    out3[(size_t)b * S_ + s] = sum * 0.125f;
}

// ============================================================
extern "C" void kernel_launch(void* const* d_in, const int* in_sizes, int n_in,
                              void* d_out, int out_size)
{
    const float* mol  = (const float*)d_in[0];
    const float* prot = (const float*)d_in[1];
    const float* Wq   = (const float*)d_in[2];
    const float* bq   = (const float*)d_in[3];
    const float* Wmv  = (const float*)d_in[4];
    const float* bmv  = (const float*)d_in[5];
    const float* Wpk  = (const float*)d_in[6];
    const float* bpk  = (const float*)d_in[7];
    const float* Wpv  = (const float*)d_in[8];
    const float* bpv  = (const float*)d_in[9];
    const float* Wmo  = (const float*)d_in[10];
    const float* bmo  = (const float*)d_in[11];
    const float* Wpo  = (const float*)d_in[12];
    const float* bpo  = (const float*)d_in[13];

    float* out = (float*)d_out;
    float* out1 = out;                                           // [B,128]
    float* out2 = out + (size_t)B_ * F_;                         // [B,S,128]
    float* out3 = out + (size_t)B_ * F_ + (size_t)B_ * S_ * F_;  // [B,S]

    cudaFuncSetAttribute(k2_fused, cudaFuncAttributeMaxDynamicSharedMemorySize,
                         K2_SMEM_BYTES);

    k1_precompute<<<B_, 256>>>(mol, Wq, bq, Wmv, bmv, Wpk, bpk, Wpo);
    k2_fused<<<dim3(NCH, B_), 256, K2_SMEM_BYTES>>>(prot, bpo, out2);
    k3_epilogue<<<B_, 256>>>(mol, Wpv, bpv, Wmo, bmo, out1);
    k4_avg<<<dim3(S_ / 256, B_), 256>>>(out3);
}